// round 16
// baseline (speedup 1.0000x reference)
#include <cuda_runtime.h>
#include <cuda_bf16.h>
#include <stdint.h>

#define P_PTS 10000
#define NPTS  100
#define MAXB  4096
#define KP1   320           // padded K for layer 1 (300 -> 5 chunks of 64)
#define K2    256
#define SLD   72            // smem row stride for A/B tiles (conflict-free ldmatrix)
#define HSL   264           // smem row stride for h buffer (256 cols + pad)

typedef unsigned long long ull;

// ------------------------------ scratch ------------------------------------
__device__ __nv_bfloat16 g_phi_h[MAXB * KP1];   // phi split, row-major [b][320]
__device__ __nv_bfloat16 g_phi_l[MAXB * KP1];
__device__ __nv_bfloat16 g_W1h[128 * KP1];      // W1 split, [n][k]
__device__ __nv_bfloat16 g_W1l[128 * KP1];
__device__ __nv_bfloat16 g_Wch[256 * K2];       // [W3|W4] split, [n][k]
__device__ __nv_bfloat16 g_Wcl[256 * K2];
__device__ float g_b34[256];

// ------------------------------ helpers -------------------------------------
__device__ __forceinline__ uint32_t smem_u32(const void* p) {
    uint32_t a;
    asm("{ .reg .u64 t; cvta.to.shared.u64 t, %1; cvt.u32.u64 %0, t; }"
        : "=r"(a) : "l"(p));
    return a;
}

#define LDSM_X4(r, a)                                                         \
    asm volatile("ldmatrix.sync.aligned.m8n8.x4.shared.b16 {%0,%1,%2,%3}, [%4];" \
                 : "=r"((r)[0]), "=r"((r)[1]), "=r"((r)[2]), "=r"((r)[3])     \
                 : "r"(a))

#define MMA_BF16(c, a, b0, b1)                                                \
    asm volatile("mma.sync.aligned.m16n8k16.row.col.f32.bf16.bf16.f32 "       \
                 "{%0,%1,%2,%3}, {%4,%5,%6,%7}, {%8,%9}, {%0,%1,%2,%3};"      \
                 : "+f"((c)[0]), "+f"((c)[1]), "+f"((c)[2]), "+f"((c)[3])     \
                 : "r"((a)[0]), "r"((a)[1]), "r"((a)[2]), "r"((a)[3]),        \
                   "r"(b0), "r"(b1))

__device__ __forceinline__ void bf16split(float v, __nv_bfloat16& hi, __nv_bfloat16& lo) {
    hi = __float2bfloat16(v);
    lo = __float2bfloat16(v - __bfloat162float(hi));
}

// ------------------------------ foveate (+ folded prep) ---------------------
// R11/R15-proven scan; prep splits weights; epilogue splits phi. UNCHANGED.
__global__ void __launch_bounds__(512) foveate_kernel(
        const float* __restrict__ x,  const float* __restrict__ lt,
        const float* __restrict__ W1, const float* __restrict__ W3,
        const float* __restrict__ W4, const float* __restrict__ b3,
        const float* __restrict__ b4) {
    __shared__ float s0[NPTS], s1[NPTS], s2[NPTS];
    __shared__ int warp_cnt[2][16];

    int b = blockIdx.x;
    int tid = threadIdx.x, lane = tid & 31, wid = tid >> 5;

    // folded prep: split weights
    {
        int g = b * 512 + tid;
        if (g < 128 * KP1) {
            int n = g / KP1, k = g - n * KP1;
            float w = (k < 300) ? W1[n * 300 + k] : 0.0f;
            __nv_bfloat16 hi, lo; bf16split(w, hi, lo);
            g_W1h[g] = hi; g_W1l[g] = lo;
        }
        if (g < 256 * K2) {
            int n = g >> 8, k = g & 255;
            float w = (k < 128) ? W3[n * 128 + k] : W4[n * 128 + (k - 128)];
            __nv_bfloat16 hi, lo; bf16split(w, hi, lo);
            g_Wch[g] = hi; g_Wcl[g] = lo;
        }
        if (g < 256) g_b34[g] = b3[g] + b4[g];
    }

    const float* xb = x + (size_t)b * 3 * P_PTS;
    float l0 = lt[b * 3 + 0], l1 = lt[b * 3 + 1], l2 = lt[b * 3 + 2];
    float lo0 = l0 - 0.25f, hi0 = l0 + 0.25f;
    float lo1 = l1 - 0.25f, hi1 = l1 + 0.25f;
    float lo2 = l2 - 0.25f, hi2 = l2 + 0.25f;
    unsigned ltm = (1u << lane) - 1u;

    int run = 0, buf = 0;
    for (int base = 0; base < P_PTS; base += 2048) {
        int p0 = base + tid * 4;
        float v0[4], v1[4], v2[4];
        unsigned m = 0;
        if (p0 < P_PTS) {
            float4 f0 = *(const float4*)(xb + p0);
            float4 f1 = *(const float4*)(xb + P_PTS + p0);
            float4 f2 = *(const float4*)(xb + 2 * P_PTS + p0);
            v0[0]=f0.x; v0[1]=f0.y; v0[2]=f0.z; v0[3]=f0.w;
            v1[0]=f1.x; v1[1]=f1.y; v1[2]=f1.z; v1[3]=f1.w;
            v2[0]=f2.x; v2[1]=f2.y; v2[2]=f2.z; v2[3]=f2.w;
#pragma unroll
            for (int i = 0; i < 4; i++) {
                bool in = (v0[i] >= lo0) && (v0[i] <= hi0) &&
                          (v1[i] >= lo1) && (v1[i] <= hi1) &&
                          (v2[i] >= lo2) && (v2[i] <= hi2);
                m |= ((unsigned)in) << i;
            }
        }
        unsigned bl0 = __ballot_sync(0xffffffffu,  m       & 1u);
        unsigned bl1 = __ballot_sync(0xffffffffu, (m >> 1) & 1u);
        unsigned bl2 = __ballot_sync(0xffffffffu, (m >> 2) & 1u);
        unsigned bl3 = __ballot_sync(0xffffffffu, (m >> 3) & 1u);
        if (lane == 0)
            warp_cnt[buf][wid] = __popc(bl0) + __popc(bl1) + __popc(bl2) + __popc(bl3);
        int excl = __popc(bl0 & ltm) + __popc(bl1 & ltm) +
                   __popc(bl2 & ltm) + __popc(bl3 & ltm);
        __syncthreads();

        int v = (lane < 16) ? warp_cnt[buf][lane] : 0;
#pragma unroll
        for (int off = 1; off < 16; off <<= 1) {
            int t = __shfl_up_sync(0xffffffffu, v, off);
            if (lane >= off) v += t;
        }
        int tot = __shfl_sync(0xffffffffu, v, 15);
        int wsrc = (wid == 0) ? 0 : (wid - 1);
        int wofft = __shfl_sync(0xffffffffu, v, wsrc);
        int woff = (wid == 0) ? 0 : wofft;

        int r = run + woff + excl;
#pragma unroll
        for (int i = 0; i < 4; i++) {
            if ((m >> i) & 1u) {
                if (r < NPTS) { s0[r] = v0[i]; s1[r] = v1[i]; s2[r] = v2[i]; }
                r++;
            }
        }
        run += tot;
        buf ^= 1;
        if (run >= NPTS) break;
    }
    __syncthreads();

    int n = run;
    if (tid < KP1) {
        float v = 0.0f;
        if (tid < 300 && n > 0) {
            int axis = tid / 100, pos = tid - axis * 100;
            int j = (n >= NPTS) ? pos : (pos % n);
            v = (axis == 0) ? s0[j] : ((axis == 1) ? s1[j] : s2[j]);
        }
        __nv_bfloat16 hi, lo; bf16split(v, hi, lo);
        g_phi_h[(size_t)b * KP1 + tid] = hi;
        g_phi_l[(size_t)b * KP1 + tid] = lo;
    }
}

// ------------------------------ fused MLP (mma.sync) ------------------------
// One kernel, BM=32, 256 threads, grid B/32 = 128.
// Phase 1: h[32,256] (hi/lo split, SMEM) = relu(phi @ W1^T + b1) | relu(l@W2^T+b2)
// Phase 2: out[32,256] = relu(h @ Wc^T + b34); A read DIRECTLY from h smem.
// Dynamic smem (bf16 elems): sAh 2304 | sAl 2304 | sBh 9216 | sBl 9216
//                            | hH 8448 | hL 8448  = 39936 (79.9 KB)
#define MLP_SMEM_BYTES (39936 * 2)

extern __shared__ __nv_bfloat16 smdy[];

__global__ void __launch_bounds__(256) mlp_tc(
        const float* __restrict__ b1, const float* __restrict__ lt,
        const float* __restrict__ W2, const float* __restrict__ b2,
        float* __restrict__ out) {
    __nv_bfloat16* sAh = smdy;
    __nv_bfloat16* sAl = smdy + 2304;
    __nv_bfloat16* sBh = smdy + 4608;
    __nv_bfloat16* sBl = smdy + 13824;
    __nv_bfloat16* hH  = smdy + 23040;   // [32][HSL]
    __nv_bfloat16* hL  = smdy + 31488;

    int tid = threadIdx.x, lane = tid & 31, w = tid >> 5;
    int row0 = blockIdx.x * 32;
    int mr = (w >> 2) * 16;       // warp row base: 0 or 16
    int nb = (w & 3) * 32;        // warp col base: 0/32/64/96

    // ================= phase 1: hidden GEMM =================
    float c[4][4] = {};

    for (int kc = 0; kc < 5; kc++) {
        {   // A: 32 rows x 8 uint4 (1/thread)
            int r = tid >> 3, q = tid & 7;
            size_t ga = (size_t)(row0 + r) * KP1 + kc * 64 + q * 8;
            *(uint4*)&sAh[r * SLD + q * 8] = *(const uint4*)&g_phi_h[ga];
            *(uint4*)&sAl[r * SLD + q * 8] = *(const uint4*)&g_phi_l[ga];
        }
#pragma unroll
        for (int j = 0; j < 4; j++) {   // B: 128 rows x 8 uint4 (4/thread)
            int idx = tid + j * 256;
            int r = idx >> 3, q = idx & 7;
            size_t gb = (size_t)r * KP1 + kc * 64 + q * 8;
            *(uint4*)&sBh[r * SLD + q * 8] = *(const uint4*)&g_W1h[gb];
            *(uint4*)&sBl[r * SLD + q * 8] = *(const uint4*)&g_W1l[gb];
        }
        __syncthreads();

#pragma unroll
        for (int ks = 0; ks < 4; ks++) {
            int k0 = ks * 16;
            uint32_t ah[4], al[4];
            int aoff = (mr + (lane & 15)) * SLD + k0 + (lane >> 4) * 8;
            LDSM_X4(ah, smem_u32(&sAh[aoff]));
            LDSM_X4(al, smem_u32(&sAl[aoff]));

            uint32_t bh[2][4], bl[2][4];
#pragma unroll
            for (int g = 0; g < 2; g++) {
                int boff = (nb + g * 16 + (lane & 7) + ((lane >> 4) << 3)) * SLD
                         + k0 + ((lane >> 3) & 1) * 8;
                LDSM_X4(bh[g], smem_u32(&sBh[boff]));
                LDSM_X4(bl[g], smem_u32(&sBl[boff]));
            }
#pragma unroll
            for (int f = 0; f < 4; f++) {
                uint32_t* BH = bh[f >> 1];
                uint32_t* BL = bl[f >> 1];
                int o = (f & 1) * 2;
                MMA_BF16(c[f], ah, BH[o], BH[o + 1]);
                MMA_BF16(c[f], ah, BL[o], BL[o + 1]);
                MMA_BF16(c[f], al, BH[o], BH[o + 1]);
            }
        }
        __syncthreads();
    }

    // phase 1 epilogue: +b1, relu, split -> h smem cols 0-127
#pragma unroll
    for (int f = 0; f < 4; f++) {
        int col = nb + f * 8 + (lane & 3) * 2;
        int rl = mr + (lane >> 2);
        float bb0 = b1[col], bb1 = b1[col + 1];
        float v00 = fmaxf(c[f][0] + bb0, 0.f), v01 = fmaxf(c[f][1] + bb1, 0.f);
        float v10 = fmaxf(c[f][2] + bb0, 0.f), v11 = fmaxf(c[f][3] + bb1, 0.f);
        __nv_bfloat16 h0, L0, h1, L1;
        bf16split(v00, h0, L0); bf16split(v01, h1, L1);
        *(__nv_bfloat162*)&hH[rl * HSL + col] = __nv_bfloat162(h0, h1);
        *(__nv_bfloat162*)&hL[rl * HSL + col] = __nv_bfloat162(L0, L1);
        bf16split(v10, h0, L0); bf16split(v11, h1, L1);
        *(__nv_bfloat162*)&hH[(rl + 8) * HSL + col] = __nv_bfloat162(h0, h1);
        *(__nv_bfloat162*)&hL[(rl + 8) * HSL + col] = __nv_bfloat162(L0, L1);
    }

    // l_out half: h cols 128-255 (direct compute into smem)
    {
        int cc = tid & 127, rh = (tid >> 7) * 16;
        float w0 = W2[cc * 3 + 0], w1 = W2[cc * 3 + 1], w2 = W2[cc * 3 + 2];
        float bc = b2[cc];
#pragma unroll
        for (int r = 0; r < 16; r++) {
            int rg = row0 + rh + r;
            float v = fmaxf(bc + lt[rg * 3] * w0 + lt[rg * 3 + 1] * w1
                               + lt[rg * 3 + 2] * w2, 0.f);
            __nv_bfloat16 hi, lo; bf16split(v, hi, lo);
            hH[(rh + r) * HSL + 128 + cc] = hi;
            hL[(rh + r) * HSL + 128 + cc] = lo;
        }
    }
    __syncthreads();   // h complete; sB free for phase 2

    // ================= phase 2: output GEMM (per column half) =================
    for (int ct = 0; ct < 2; ct++) {
        float c2[4][4] = {};

        for (int kc = 0; kc < 4; kc++) {
#pragma unroll
            for (int j = 0; j < 4; j++) {   // B: Wc[ct half] chunk (4/thread)
                int idx = tid + j * 256;
                int r = idx >> 3, q = idx & 7;
                size_t gb = (size_t)(ct * 128 + r) * K2 + kc * 64 + q * 8;
                *(uint4*)&sBh[r * SLD + q * 8] = *(const uint4*)&g_Wch[gb];
                *(uint4*)&sBl[r * SLD + q * 8] = *(const uint4*)&g_Wcl[gb];
            }
            __syncthreads();

#pragma unroll
            for (int ks = 0; ks < 4; ks++) {
                int kabs = kc * 64 + ks * 16;
                uint32_t ah[4], al[4];
                int aoff = (mr + (lane & 15)) * HSL + kabs + (lane >> 4) * 8;
                LDSM_X4(ah, smem_u32(&hH[aoff]));      // A straight from h smem
                LDSM_X4(al, smem_u32(&hL[aoff]));

                uint32_t bh[2][4], bl[2][4];
#pragma unroll
                for (int g = 0; g < 2; g++) {
                    int boff = (nb + g * 16 + (lane & 7) + ((lane >> 4) << 3)) * SLD
                             + ks * 16 + ((lane >> 3) & 1) * 8;
                    LDSM_X4(bh[g], smem_u32(&sBh[boff]));
                    LDSM_X4(bl[g], smem_u32(&sBl[boff]));
                }
#pragma unroll
                for (int f = 0; f < 4; f++) {
                    uint32_t* BH = bh[f >> 1];
                    uint32_t* BL = bl[f >> 1];
                    int o = (f & 1) * 2;
                    MMA_BF16(c2[f], ah, BH[o], BH[o + 1]);
                    MMA_BF16(c2[f], ah, BL[o], BL[o + 1]);
                    MMA_BF16(c2[f], al, BH[o], BH[o + 1]);
                }
            }
            __syncthreads();
        }

        // epilogue: +b34, relu, fp32 float2 stores
#pragma unroll
        for (int f = 0; f < 4; f++) {
            int colg = ct * 128 + nb + f * 8 + (lane & 3) * 2;
            int rA = row0 + mr + (lane >> 2);
            float bb0 = g_b34[colg], bb1 = g_b34[colg + 1];
            *(float2*)&out[(size_t)rA * 256 + colg] =
                make_float2(fmaxf(c2[f][0] + bb0, 0.f), fmaxf(c2[f][1] + bb1, 0.f));
            *(float2*)&out[(size_t)(rA + 8) * 256 + colg] =
                make_float2(fmaxf(c2[f][2] + bb0, 0.f), fmaxf(c2[f][3] + bb1, 0.f));
        }
    }
}

// ------------------------------ launch --------------------------------------
extern "C" void kernel_launch(void* const* d_in, const int* in_sizes, int n_in,
                              void* d_out, int out_size) {
    const float* x  = (const float*)d_in[0];
    const float* lt = (const float*)d_in[1];
    const float* W1 = (const float*)d_in[2];
    const float* b1 = (const float*)d_in[3];
    const float* W2 = (const float*)d_in[4];
    const float* b2 = (const float*)d_in[5];
    const float* W3 = (const float*)d_in[6];
    const float* b3 = (const float*)d_in[7];
    const float* W4 = (const float*)d_in[8];
    const float* b4 = (const float*)d_in[9];
    float* out = (float*)d_out;

    int B = in_sizes[0] / (3 * P_PTS);
    if (B > MAXB) B = MAXB;

    cudaFuncSetAttribute(mlp_tc, cudaFuncAttributeMaxDynamicSharedMemorySize,
                         MLP_SMEM_BYTES);

    foveate_kernel<<<B, 512>>>(x, lt, W1, W3, W4, b3, b4);
    mlp_tc<<<B / 32, 256, MLP_SMEM_BYTES>>>(b1, lt, W2, b2, out);
}

// round 17
// speedup vs baseline: 1.0316x; 1.0316x over previous
#include <cuda_runtime.h>
#include <cuda_bf16.h>
#include <stdint.h>

#define P_PTS 10000
#define NPTS  100
#define MAXB  4096
#define KP1   320           // padded K for layer 1 (300 -> 5 chunks of 64)
#define K2    256
#define SLD   72            // smem row stride (144B: 16B-aligned, ldmatrix conflict-free)

typedef unsigned long long ull;

// ------------------------------ scratch ------------------------------------
__device__ __nv_bfloat16 g_phi_h[MAXB * KP1];   // phi split, row-major [b][320]
__device__ __nv_bfloat16 g_phi_l[MAXB * KP1];
__device__ __nv_bfloat16 g_W1h[128 * KP1];      // W1 split, [n][k]
__device__ __nv_bfloat16 g_W1l[128 * KP1];
__device__ __nv_bfloat16 g_Wch[256 * K2];       // [W3|W4] split, [n][k]
__device__ __nv_bfloat16 g_Wcl[256 * K2];
__device__ __nv_bfloat16 g_hh[MAXB * K2];       // hidden split, [b][256]
__device__ __nv_bfloat16 g_hl[MAXB * K2];
__device__ float g_b34[256];

// ------------------------------ helpers -------------------------------------
__device__ __forceinline__ uint32_t smem_u32(const void* p) {
    uint32_t a;
    asm("{ .reg .u64 t; cvta.to.shared.u64 t, %1; cvt.u32.u64 %0, t; }"
        : "=r"(a) : "l"(p));
    return a;
}

#define LDSM_X4(r, a)                                                         \
    asm volatile("ldmatrix.sync.aligned.m8n8.x4.shared.b16 {%0,%1,%2,%3}, [%4];" \
                 : "=r"((r)[0]), "=r"((r)[1]), "=r"((r)[2]), "=r"((r)[3])     \
                 : "r"(a))

#define MMA_BF16(c, a, b0, b1)                                                \
    asm volatile("mma.sync.aligned.m16n8k16.row.col.f32.bf16.bf16.f32 "       \
                 "{%0,%1,%2,%3}, {%4,%5,%6,%7}, {%8,%9}, {%0,%1,%2,%3};"      \
                 : "+f"((c)[0]), "+f"((c)[1]), "+f"((c)[2]), "+f"((c)[3])     \
                 : "r"((a)[0]), "r"((a)[1]), "r"((a)[2]), "r"((a)[3]),        \
                   "r"(b0), "r"(b1))

__device__ __forceinline__ void bf16split(float v, __nv_bfloat16& hi, __nv_bfloat16& lo) {
    hi = __float2bfloat16(v);
    lo = __float2bfloat16(v - __bfloat162float(hi));
}

// ------------------------------ foveate (+ folded prep) ---------------------
// R11/R15-proven scan. ONLY change: __launch_bounds__(512, 4) caps regs at 32
// -> 4 CTAs/SM (full occupancy) instead of 3.
__global__ void __launch_bounds__(512, 4) foveate_kernel(
        const float* __restrict__ x,  const float* __restrict__ lt,
        const float* __restrict__ W1, const float* __restrict__ W3,
        const float* __restrict__ W4, const float* __restrict__ b3,
        const float* __restrict__ b4) {
    __shared__ float s0[NPTS], s1[NPTS], s2[NPTS];
    __shared__ int warp_cnt[2][16];

    int b = blockIdx.x;
    int tid = threadIdx.x, lane = tid & 31, wid = tid >> 5;

    // folded prep: split weights
    {
        int g = b * 512 + tid;
        if (g < 128 * KP1) {
            int n = g / KP1, k = g - n * KP1;
            float w = (k < 300) ? W1[n * 300 + k] : 0.0f;
            __nv_bfloat16 hi, lo; bf16split(w, hi, lo);
            g_W1h[g] = hi; g_W1l[g] = lo;
        }
        if (g < 256 * K2) {
            int n = g >> 8, k = g & 255;
            float w = (k < 128) ? W3[n * 128 + k] : W4[n * 128 + (k - 128)];
            __nv_bfloat16 hi, lo; bf16split(w, hi, lo);
            g_Wch[g] = hi; g_Wcl[g] = lo;
        }
        if (g < 256) g_b34[g] = b3[g] + b4[g];
    }

    const float* xb = x + (size_t)b * 3 * P_PTS;
    float l0 = lt[b * 3 + 0], l1 = lt[b * 3 + 1], l2 = lt[b * 3 + 2];
    float lo0 = l0 - 0.25f, hi0 = l0 + 0.25f;
    float lo1 = l1 - 0.25f, hi1 = l1 + 0.25f;
    float lo2 = l2 - 0.25f, hi2 = l2 + 0.25f;
    unsigned ltm = (1u << lane) - 1u;

    int run = 0, buf = 0;
    for (int base = 0; base < P_PTS; base += 2048) {
        int p0 = base + tid * 4;
        float v0[4], v1[4], v2[4];
        unsigned m = 0;
        if (p0 < P_PTS) {
            float4 f0 = *(const float4*)(xb + p0);
            float4 f1 = *(const float4*)(xb + P_PTS + p0);
            float4 f2 = *(const float4*)(xb + 2 * P_PTS + p0);
            v0[0]=f0.x; v0[1]=f0.y; v0[2]=f0.z; v0[3]=f0.w;
            v1[0]=f1.x; v1[1]=f1.y; v1[2]=f1.z; v1[3]=f1.w;
            v2[0]=f2.x; v2[1]=f2.y; v2[2]=f2.z; v2[3]=f2.w;
#pragma unroll
            for (int i = 0; i < 4; i++) {
                bool in = (v0[i] >= lo0) && (v0[i] <= hi0) &&
                          (v1[i] >= lo1) && (v1[i] <= hi1) &&
                          (v2[i] >= lo2) && (v2[i] <= hi2);
                m |= ((unsigned)in) << i;
            }
        }
        unsigned bl0 = __ballot_sync(0xffffffffu,  m       & 1u);
        unsigned bl1 = __ballot_sync(0xffffffffu, (m >> 1) & 1u);
        unsigned bl2 = __ballot_sync(0xffffffffu, (m >> 2) & 1u);
        unsigned bl3 = __ballot_sync(0xffffffffu, (m >> 3) & 1u);
        if (lane == 0)
            warp_cnt[buf][wid] = __popc(bl0) + __popc(bl1) + __popc(bl2) + __popc(bl3);
        int excl = __popc(bl0 & ltm) + __popc(bl1 & ltm) +
                   __popc(bl2 & ltm) + __popc(bl3 & ltm);
        __syncthreads();

        int v = (lane < 16) ? warp_cnt[buf][lane] : 0;
#pragma unroll
        for (int off = 1; off < 16; off <<= 1) {
            int t = __shfl_up_sync(0xffffffffu, v, off);
            if (lane >= off) v += t;
        }
        int tot = __shfl_sync(0xffffffffu, v, 15);
        int wsrc = (wid == 0) ? 0 : (wid - 1);
        int wofft = __shfl_sync(0xffffffffu, v, wsrc);
        int woff = (wid == 0) ? 0 : wofft;

        int r = run + woff + excl;
#pragma unroll
        for (int i = 0; i < 4; i++) {
            if ((m >> i) & 1u) {
                if (r < NPTS) { s0[r] = v0[i]; s1[r] = v1[i]; s2[r] = v2[i]; }
                r++;
            }
        }
        run += tot;
        buf ^= 1;
        if (run >= NPTS) break;
    }
    __syncthreads();

    int n = run;
    if (tid < KP1) {
        float v = 0.0f;
        if (tid < 300 && n > 0) {
            int axis = tid / 100, pos = tid - axis * 100;
            int j = (n >= NPTS) ? pos : (pos % n);
            v = (axis == 0) ? s0[j] : ((axis == 1) ? s1[j] : s2[j]);
        }
        __nv_bfloat16 hi, lo; bf16split(v, hi, lo);
        g_phi_h[(size_t)b * KP1 + tid] = hi;
        g_phi_l[(size_t)b * KP1 + tid] = lo;
    }
}

// ------------------------------ hidden (mma.sync) ---------------------------
// R15-proven. D[32,128] = phi[32,320] @ W1^T, 3-term bf16 split, fp32 accum.
// 8 warps: warp = 16 rows x 32 cols. grid = B/32 = 128.
__global__ void __launch_bounds__(256) hidden_tc(
        const float* __restrict__ b1, const float* __restrict__ lt,
        const float* __restrict__ W2, const float* __restrict__ b2) {
    __shared__ __nv_bfloat16 sAh[32 * SLD], sAl[32 * SLD];
    __shared__ __nv_bfloat16 sBh[128 * SLD], sBl[128 * SLD];

    int tid = threadIdx.x, lane = tid & 31, w = tid >> 5;
    int row0 = blockIdx.x * 32;
    int mr = (w >> 2) * 16;       // warp row base: 0 or 16
    int nb = (w & 3) * 32;        // warp col base: 0/32/64/96

    float c[4][4] = {};           // 4 n-frags x 4

    for (int kc = 0; kc < 5; kc++) {
        {   // A: 32 rows x 8 uint4 = 256 loads (1/thread)
            int r = tid >> 3, q = tid & 7;
            size_t ga = (size_t)(row0 + r) * KP1 + kc * 64 + q * 8;
            *(uint4*)&sAh[r * SLD + q * 8] = *(const uint4*)&g_phi_h[ga];
            *(uint4*)&sAl[r * SLD + q * 8] = *(const uint4*)&g_phi_l[ga];
        }
#pragma unroll
        for (int j = 0; j < 4; j++) {   // B: 128 rows x 8 uint4 (4/thread)
            int idx = tid + j * 256;
            int r = idx >> 3, q = idx & 7;
            size_t gb = (size_t)r * KP1 + kc * 64 + q * 8;
            *(uint4*)&sBh[r * SLD + q * 8] = *(const uint4*)&g_W1h[gb];
            *(uint4*)&sBl[r * SLD + q * 8] = *(const uint4*)&g_W1l[gb];
        }
        __syncthreads();

#pragma unroll
        for (int ks = 0; ks < 4; ks++) {
            int k0 = ks * 16;
            uint32_t ah[4], al[4];
            int aoff = (mr + (lane & 15)) * SLD + k0 + (lane >> 4) * 8;
            LDSM_X4(ah, smem_u32(&sAh[aoff]));
            LDSM_X4(al, smem_u32(&sAl[aoff]));

            uint32_t bh[2][4], bl[2][4];
#pragma unroll
            for (int g = 0; g < 2; g++) {
                int boff = (nb + g * 16 + (lane & 7) + ((lane >> 4) << 3)) * SLD
                         + k0 + ((lane >> 3) & 1) * 8;
                LDSM_X4(bh[g], smem_u32(&sBh[boff]));
                LDSM_X4(bl[g], smem_u32(&sBl[boff]));
            }
#pragma unroll
            for (int f = 0; f < 4; f++) {
                uint32_t* BH = bh[f >> 1];
                uint32_t* BL = bl[f >> 1];
                int o = (f & 1) * 2;
                MMA_BF16(c[f], ah, BH[o], BH[o + 1]);
                MMA_BF16(c[f], ah, BL[o], BL[o + 1]);
                MMA_BF16(c[f], al, BH[o], BH[o + 1]);
            }
        }
        __syncthreads();
    }

    // epilogue: +b1, relu, bf16 split -> g_hh/g_hl cols 0-127
#pragma unroll
    for (int f = 0; f < 4; f++) {
        int col = nb + f * 8 + (lane & 3) * 2;
        int rA = row0 + mr + (lane >> 2);
        float bb0 = b1[col], bb1 = b1[col + 1];
        float v00 = fmaxf(c[f][0] + bb0, 0.f), v01 = fmaxf(c[f][1] + bb1, 0.f);
        float v10 = fmaxf(c[f][2] + bb0, 0.f), v11 = fmaxf(c[f][3] + bb1, 0.f);
        __nv_bfloat16 h0, l0_, h1, l1_;
        bf16split(v00, h0, l0_); bf16split(v01, h1, l1_);
        *(__nv_bfloat162*)&g_hh[(size_t)rA * K2 + col] = __nv_bfloat162(h0, h1);
        *(__nv_bfloat162*)&g_hl[(size_t)rA * K2 + col] = __nv_bfloat162(l0_, l1_);
        bf16split(v10, h0, l0_); bf16split(v11, h1, l1_);
        *(__nv_bfloat162*)&g_hh[(size_t)(rA + 8) * K2 + col] = __nv_bfloat162(h0, h1);
        *(__nv_bfloat162*)&g_hl[(size_t)(rA + 8) * K2 + col] = __nv_bfloat162(l0_, l1_);
    }

    // l_out half: h cols 128-255
    {
        int cc = tid & 127, rh = (tid >> 7) * 16;
        float w0 = W2[cc * 3 + 0], w1 = W2[cc * 3 + 1], w2 = W2[cc * 3 + 2];
        float bc = b2[cc];
#pragma unroll
        for (int r = 0; r < 16; r++) {
            int rg = row0 + rh + r;
            float v = fmaxf(bc + lt[rg * 3] * w0 + lt[rg * 3 + 1] * w1
                               + lt[rg * 3 + 2] * w2, 0.f);
            __nv_bfloat16 hi, lo; bf16split(v, hi, lo);
            g_hh[(size_t)rg * K2 + 128 + cc] = hi;
            g_hl[(size_t)rg * K2 + 128 + cc] = lo;
        }
    }
}

// ------------------------------ output (mma.sync) ---------------------------
// R15-proven. D[32,128] = h[32,256] @ Wc^T(col tile ct). grid (B/32, 2).
__global__ void __launch_bounds__(256) out_tc(float* __restrict__ out) {
    __shared__ __nv_bfloat16 sAh[32 * SLD], sAl[32 * SLD];
    __shared__ __nv_bfloat16 sBh[128 * SLD], sBl[128 * SLD];

    int tid = threadIdx.x, lane = tid & 31, w = tid >> 5;
    int row0 = blockIdx.x * 32;
    int ct = blockIdx.y;          // column tile (0/1)
    int mr = (w >> 2) * 16;
    int nb = (w & 3) * 32;

    float c[4][4] = {};

    for (int kc = 0; kc < 4; kc++) {
        {
            int r = tid >> 3, q = tid & 7;
            size_t ga = (size_t)(row0 + r) * K2 + kc * 64 + q * 8;
            *(uint4*)&sAh[r * SLD + q * 8] = *(const uint4*)&g_hh[ga];
            *(uint4*)&sAl[r * SLD + q * 8] = *(const uint4*)&g_hl[ga];
        }
#pragma unroll
        for (int j = 0; j < 4; j++) {
            int idx = tid + j * 256;
            int r = idx >> 3, q = idx & 7;
            size_t gb = (size_t)(ct * 128 + r) * K2 + kc * 64 + q * 8;
            *(uint4*)&sBh[r * SLD + q * 8] = *(const uint4*)&g_Wch[gb];
            *(uint4*)&sBl[r * SLD + q * 8] = *(const uint4*)&g_Wcl[gb];
        }
        __syncthreads();

#pragma unroll
        for (int ks = 0; ks < 4; ks++) {
            int k0 = ks * 16;
            uint32_t ah[4], al[4];
            int aoff = (mr + (lane & 15)) * SLD + k0 + (lane >> 4) * 8;
            LDSM_X4(ah, smem_u32(&sAh[aoff]));
            LDSM_X4(al, smem_u32(&sAl[aoff]));

            uint32_t bh[2][4], bl[2][4];
#pragma unroll
            for (int g = 0; g < 2; g++) {
                int boff = (nb + g * 16 + (lane & 7) + ((lane >> 4) << 3)) * SLD
                         + k0 + ((lane >> 3) & 1) * 8;
                LDSM_X4(bh[g], smem_u32(&sBh[boff]));
                LDSM_X4(bl[g], smem_u32(&sBl[boff]));
            }
#pragma unroll
            for (int f = 0; f < 4; f++) {
                uint32_t* BH = bh[f >> 1];
                uint32_t* BL = bl[f >> 1];
                int o = (f & 1) * 2;
                MMA_BF16(c[f], ah, BH[o], BH[o + 1]);
                MMA_BF16(c[f], ah, BL[o], BL[o + 1]);
                MMA_BF16(c[f], al, BH[o], BH[o + 1]);
            }
        }
        __syncthreads();
    }

    // epilogue: +b34, relu, fp32 float2 stores
#pragma unroll
    for (int f = 0; f < 4; f++) {
        int colg = ct * 128 + nb + f * 8 + (lane & 3) * 2;
        int rA = row0 + mr + (lane >> 2);
        float bb0 = g_b34[colg], bb1 = g_b34[colg + 1];
        *(float2*)&out[(size_t)rA * 256 + colg] =
            make_float2(fmaxf(c[f][0] + bb0, 0.f), fmaxf(c[f][1] + bb1, 0.f));
        *(float2*)&out[(size_t)(rA + 8) * 256 + colg] =
            make_float2(fmaxf(c[f][2] + bb0, 0.f), fmaxf(c[f][3] + bb1, 0.f));
    }
}

// ------------------------------ launch --------------------------------------
extern "C" void kernel_launch(void* const* d_in, const int* in_sizes, int n_in,
                              void* d_out, int out_size) {
    const float* x  = (const float*)d_in[0];
    const float* lt = (const float*)d_in[1];
    const float* W1 = (const float*)d_in[2];
    const float* b1 = (const float*)d_in[3];
    const float* W2 = (const float*)d_in[4];
    const float* b2 = (const float*)d_in[5];
    const float* W3 = (const float*)d_in[6];
    const float* b3 = (const float*)d_in[7];
    const float* W4 = (const float*)d_in[8];
    const float* b4 = (const float*)d_in[9];
    float* out = (float*)d_out;

    int B = in_sizes[0] / (3 * P_PTS);
    if (B > MAXB) B = MAXB;

    foveate_kernel<<<B, 512>>>(x, lt, W1, W3, W4, b3, b4);
    hidden_tc<<<B / 32, 256>>>(b1, lt, W2, b2);
    out_tc<<<dim3(B / 32, 2), 256>>>(out);
}